// round 6
// baseline (speedup 1.0000x reference)
#include <cuda_runtime.h>

// NonLocalBlock: conv1(1x1) -> flash self-attention (unscaled, K=V=Q) ->
// raw reshape -> conv2(1x1) -> *scale + residual.
// B=8, C=256, C2=128, N=4096. All fp32.

namespace {
constexpr int B_  = 8;
constexpr int C_  = 256;
constexpr int C2_ = 128;
constexpr int N_  = 4096;
}

// Scratch (allocation-free): Y = conv1 output in [b][n][c2] layout,
// ATT = attention output stored flat [b][n*C2 + c2] (== the torch-bug reshape order).
__device__ float g_y[B_ * N_ * C2_];
__device__ float g_att[B_ * N_ * C2_];

// ---------------------------------------------------------------------------
// conv1: y[b][n][o] = b1[o] + sum_c x[b][c][n] * W1[o][c]
// block: 64 n  x 128 o (all o), 256 threads, 4x8 per thread
// ---------------------------------------------------------------------------
__global__ __launch_bounds__(256) void conv1_kernel(const float* __restrict__ x,
                                                    const float* __restrict__ W1,
                                                    const float* __restrict__ b1) {
    __shared__ float Xs[32 * 68];    // [c-chunk][n] pad->68
    __shared__ float Wt[32 * 132];   // [c-chunk][o] transposed, pad->132

    const int t  = threadIdx.x;
    const int n0 = blockIdx.x * 64;
    const int b  = blockIdx.y;
    const int ty = t >> 4, tx = t & 15;
    const int r0 = ty * 4;   // n offset
    const int o0 = tx * 8;   // o offset
    const float* xb = x + (size_t)b * C_ * N_;

    float acc[4][8];
#pragma unroll
    for (int i = 0; i < 4; i++)
#pragma unroll
        for (int j = 0; j < 8; j++) acc[i][j] = 0.f;

    for (int c0 = 0; c0 < C_; c0 += 32) {
        __syncthreads();
        // X chunk: rows contiguous in n -> coalesced float4
        for (int e = t; e < 32 * 16; e += 256) {
            int cc = e >> 4, k4 = (e & 15) << 2;
            *(float4*)&Xs[cc * 68 + k4] =
                *(const float4*)(xb + (size_t)(c0 + cc) * N_ + n0 + k4);
        }
        // W1 chunk transposed: read float4 along c, scatter 4 STS
        for (int e = t; e < 128 * 8; e += 256) {
            int o = e >> 3, c4 = (e & 7) << 2;
            float4 w = *(const float4*)(W1 + (size_t)o * C_ + c0 + c4);
            Wt[(c4 + 0) * 132 + o] = w.x;
            Wt[(c4 + 1) * 132 + o] = w.y;
            Wt[(c4 + 2) * 132 + o] = w.z;
            Wt[(c4 + 3) * 132 + o] = w.w;
        }
        __syncthreads();
#pragma unroll 8
        for (int cc = 0; cc < 32; cc++) {
            float xv[4];
#pragma unroll
            for (int i = 0; i < 4; i++) xv[i] = Xs[cc * 68 + r0 + i];
            float4 wa = *(float4*)&Wt[cc * 132 + o0];
            float4 wb = *(float4*)&Wt[cc * 132 + o0 + 4];
            float wv[8] = {wa.x, wa.y, wa.z, wa.w, wb.x, wb.y, wb.z, wb.w};
#pragma unroll
            for (int i = 0; i < 4; i++)
#pragma unroll
                for (int j = 0; j < 8; j++) acc[i][j] += xv[i] * wv[j];
        }
    }

    float bv[8];
#pragma unroll
    for (int j = 0; j < 8; j++) bv[j] = b1[o0 + j];
#pragma unroll
    for (int i = 0; i < 4; i++) {
        float* dst = g_y + (size_t)(b * N_ + n0 + r0 + i) * C2_ + o0;
        *(float4*)dst = make_float4(acc[i][0] + bv[0], acc[i][1] + bv[1],
                                    acc[i][2] + bv[2], acc[i][3] + bv[3]);
        *(float4*)(dst + 4) = make_float4(acc[i][4] + bv[4], acc[i][5] + bv[5],
                                          acc[i][6] + bv[6], acc[i][7] + bv[7]);
    }
}

// ---------------------------------------------------------------------------
// flash self-attention: out[n][c] = sum_m softmax_m(y[n].y[m]) * y[m][c]
// block: 64 queries, stream 64-key chunks (K == V, loaded once per chunk).
// 256 threads: S phase 4x4 (ty->rows, tx->cols), PV phase 4x8.
// ---------------------------------------------------------------------------
__global__ __launch_bounds__(256, 2) void attn_kernel() {
    extern __shared__ float sm[];
    float* Qs  = sm;              // [64][132]  natural (query, feat)
    float* Kst = sm + 64 * 132;   // [128][69]  transposed (feat, key), odd stride
    float* Ps  = Kst + 128 * 69;  // [64][68]   P tile

    const int t  = threadIdx.x;
    const int n0 = blockIdx.x * 64;
    const int b  = blockIdx.y;
    const int ty = t >> 4, tx = t & 15;
    const int r0  = ty * 4;   // query rows
    const int c0  = tx * 4;   // S cols (keys)
    const int c0v = tx * 8;   // PV cols (features)
    const float* yb = g_y + (size_t)b * N_ * C2_;

    // load Q tile
    for (int e = t; e < 64 * 32; e += 256) {
        int r = e >> 5, k4 = (e & 31) << 2;
        *(float4*)&Qs[r * 132 + k4] = *(const float4*)(yb + (size_t)(n0 + r) * C2_ + k4);
    }

    float m_old[4], l[4], acc[4][8];
#pragma unroll
    for (int i = 0; i < 4; i++) {
        m_old[i] = -1e30f;
        l[i] = 0.f;
#pragma unroll
        for (int m = 0; m < 8; m++) acc[i][m] = 0.f;
    }

    for (int j0 = 0; j0 < N_; j0 += 64) {
        __syncthreads();  // protect Kst/Ps reuse
        // load K chunk transposed: [feat][key]
        for (int e = t; e < 64 * 32; e += 256) {
            int j = e >> 5, k4 = (e & 31) << 2;
            float4 v = *(const float4*)(yb + (size_t)(j0 + j) * C2_ + k4);
            Kst[(k4 + 0) * 69 + j] = v.x;
            Kst[(k4 + 1) * 69 + j] = v.y;
            Kst[(k4 + 2) * 69 + j] = v.z;
            Kst[(k4 + 3) * 69 + j] = v.w;
        }
        __syncthreads();

        // ---- S = Q K^T (64x64, 4x4 per thread) ----
        float s[4][4];
#pragma unroll
        for (int i = 0; i < 4; i++)
#pragma unroll
            for (int j = 0; j < 4; j++) s[i][j] = 0.f;
#pragma unroll 4
        for (int k = 0; k < 128; k++) {
            float q[4], kk[4];
#pragma unroll
            for (int i = 0; i < 4; i++) q[i] = Qs[(r0 + i) * 132 + k];
#pragma unroll
            for (int j = 0; j < 4; j++) kk[j] = Kst[k * 69 + c0 + j];
#pragma unroll
            for (int i = 0; i < 4; i++)
#pragma unroll
                for (int j = 0; j < 4; j++) s[i][j] += q[i] * kk[j];
        }

        // ---- online softmax (reduce across the 16 tx lanes = half-warp) ----
        float fct[4];
#pragma unroll
        for (int i = 0; i < 4; i++) {
            float mc = fmaxf(fmaxf(s[i][0], s[i][1]), fmaxf(s[i][2], s[i][3]));
#pragma unroll
            for (int off = 8; off > 0; off >>= 1)
                mc = fmaxf(mc, __shfl_xor_sync(0xffffffffu, mc, off));
            float mnew = fmaxf(m_old[i], mc);
            fct[i] = __expf(m_old[i] - mnew);
            m_old[i] = mnew;
        }
#pragma unroll
        for (int i = 0; i < 4; i++) {
            float p0 = __expf(s[i][0] - m_old[i]);
            float p1 = __expf(s[i][1] - m_old[i]);
            float p2 = __expf(s[i][2] - m_old[i]);
            float p3 = __expf(s[i][3] - m_old[i]);
            *(float4*)&Ps[(r0 + i) * 68 + c0] = make_float4(p0, p1, p2, p3);
            float ps = (p0 + p1) + (p2 + p3);
#pragma unroll
            for (int off = 8; off > 0; off >>= 1)
                ps += __shfl_xor_sync(0xffffffffu, ps, off);
            l[i] = l[i] * fct[i] + ps;
#pragma unroll
            for (int m = 0; m < 8; m++) acc[i][m] *= fct[i];
        }
        __syncthreads();

        // ---- acc += P * K (V == K), 4x8 per thread ----
#pragma unroll 2
        for (int j = 0; j < 64; j++) {
            float pi[4], kv[8];
#pragma unroll
            for (int i = 0; i < 4; i++) pi[i] = Ps[(r0 + i) * 68 + j];
#pragma unroll
            for (int m = 0; m < 8; m++) kv[m] = Kst[(c0v + m) * 69 + j];
#pragma unroll
            for (int i = 0; i < 4; i++)
#pragma unroll
                for (int m = 0; m < 8; m++) acc[i][m] += pi[i] * kv[m];
        }
    }

    // epilogue: normalize and store flat [n][c2] (== torch-bug reshape order)
    float* ob = g_att + (size_t)b * N_ * C2_;
#pragma unroll
    for (int i = 0; i < 4; i++) {
        float inv = 1.0f / l[i];
        float* dst = ob + (size_t)(n0 + r0 + i) * C2_ + c0v;
        *(float4*)dst = make_float4(acc[i][0] * inv, acc[i][1] * inv,
                                    acc[i][2] * inv, acc[i][3] * inv);
        *(float4*)(dst + 4) = make_float4(acc[i][4] * inv, acc[i][5] * inv,
                                          acc[i][6] * inv, acc[i][7] * inv);
    }
}

// ---------------------------------------------------------------------------
// conv2 + scale + residual:
// out[b][o][n] = scale[o]*(sum_c W2[o][c]*ATT[b][c*4096+n] + b2[o]) + x[b][o][n]
// block: 64 o x 64 n, 256 threads, 4x4 per thread, full c=128 in smem.
// ---------------------------------------------------------------------------
__global__ __launch_bounds__(256) void conv2_kernel(const float* __restrict__ x,
                                                    const float* __restrict__ W2,
                                                    const float* __restrict__ b2,
                                                    const float* __restrict__ scale,
                                                    float* __restrict__ out) {
    extern __shared__ float sm[];
    float* Ss = sm;              // [128][68] : ATT flat rows (reinterp channel, n)
    float* Ws = sm + 128 * 68;   // [64][132] : W2 tile

    const int t  = threadIdx.x;
    const int n0 = blockIdx.x * 64;
    const int o0 = blockIdx.y * 64;
    const int b  = blockIdx.z;
    const int ty = t >> 4, tx = t & 15;
    const int r0 = ty * 4;   // o
    const int c0 = tx * 4;   // n
    const float* sb = g_att + (size_t)b * N_ * C2_;  // flat 524288 per batch

    for (int e = t; e < 128 * 16; e += 256) {
        int row = e >> 4, k4 = (e & 15) << 2;
        *(float4*)&Ss[row * 68 + k4] = *(const float4*)(sb + (size_t)row * N_ + n0 + k4);
    }
    for (int e = t; e < 64 * 32; e += 256) {
        int o = e >> 5, c4 = (e & 31) << 2;
        *(float4*)&Ws[o * 132 + c4] = *(const float4*)(W2 + (size_t)(o0 + o) * C2_ + c4);
    }
    __syncthreads();

    float acc[4][4];
#pragma unroll
    for (int i = 0; i < 4; i++)
#pragma unroll
        for (int j = 0; j < 4; j++) acc[i][j] = 0.f;

#pragma unroll 4
    for (int c = 0; c < 128; c++) {
        float w[4];
#pragma unroll
        for (int i = 0; i < 4; i++) w[i] = Ws[(r0 + i) * 132 + c];
        float4 sv = *(float4*)&Ss[c * 68 + c0];
#pragma unroll
        for (int i = 0; i < 4; i++) {
            acc[i][0] += w[i] * sv.x;
            acc[i][1] += w[i] * sv.y;
            acc[i][2] += w[i] * sv.z;
            acc[i][3] += w[i] * sv.w;
        }
    }

#pragma unroll
    for (int i = 0; i < 4; i++) {
        int o = o0 + r0 + i;
        float sc = scale[o];
        float bi = b2[o];
        size_t idx = ((size_t)(b * C_ + o)) * N_ + n0 + c0;
        float4 xv = *(const float4*)(x + idx);
        float4 r;
        r.x = sc * (acc[i][0] + bi) + xv.x;
        r.y = sc * (acc[i][1] + bi) + xv.y;
        r.z = sc * (acc[i][2] + bi) + xv.z;
        r.w = sc * (acc[i][3] + bi) + xv.w;
        *(float4*)(out + idx) = r;
    }
}

// ---------------------------------------------------------------------------
extern "C" void kernel_launch(void* const* d_in, const int* in_sizes, int n_in,
                              void* d_out, int out_size) {
    const float* x     = (const float*)d_in[0];  // [8,256,64,64]
    const float* W1    = (const float*)d_in[1];  // [128,256]
    const float* b1    = (const float*)d_in[2];  // [128]
    const float* W2    = (const float*)d_in[3];  // [256,128]
    const float* b2    = (const float*)d_in[4];  // [256]
    const float* scale = (const float*)d_in[5];  // [256]
    float* out = (float*)d_out;

    constexpr int ATTN_SMEM  = (64 * 132 + 128 * 69 + 64 * 68) * 4;  // 86528
    constexpr int CONV2_SMEM = (128 * 68 + 64 * 132) * 4;            // 68608
    cudaFuncSetAttribute(attn_kernel, cudaFuncAttributeMaxDynamicSharedMemorySize, ATTN_SMEM);
    cudaFuncSetAttribute(conv2_kernel, cudaFuncAttributeMaxDynamicSharedMemorySize, CONV2_SMEM);

    conv1_kernel<<<dim3(N_ / 64, B_), 256>>>(x, W1, b1);
    attn_kernel<<<dim3(N_ / 64, B_), 256, ATTN_SMEM>>>();
    conv2_kernel<<<dim3(N_ / 64, C_ / 64, B_), 256, CONV2_SMEM>>>(x, W2, b2, scale, out);
}

// round 10
// speedup vs baseline: 4.3571x; 4.3571x over previous
#include <cuda_runtime.h>
#include <cuda_bf16.h>
#include <cstdint>

// NonLocalBlock on GB300 (plain sm_103 ISA — no tcgen05 available in this
// toolchain): conv1(1x1) -> flash self-attention via mma.sync bf16 HMMA with
// hi/lo 3-pass (fp32-grade accuracy) and fixed-base softmax (Cauchy-Schwarz
// norm bound -> no accumulator rescale) -> conv2 + scale + residual.
// B=8, C=256, C2=128, N=4096, fp32 I/O.

namespace {
constexpr int B_  = 8;
constexpr int C_  = 256;
constexpr int C2_ = 128;
constexpr int N_  = 4096;
constexpr int QT  = 128;          // queries per block
constexpr int KT  = 64;           // keys per chunk
constexpr int NCHUNK = N_ / KT;   // 64

// attention smem layout (bytes): row stride 256B (128 feats bf16), XOR swizzle
constexpr int OFF_QHI = 0;               // 128 x 256B = 32KB
constexpr int OFF_QLO = 32768;
constexpr int OFF_YHI = 65536;           // 64 x 256B = 16KB
constexpr int OFF_YLO = 81920;
constexpr int ATTN_DYN = 98304;
}

__device__ float g_y[B_ * N_ * C2_];    // conv1 out, [b][n][c2]
__device__ float g_att[B_ * N_ * C2_];  // attention out, flat (torch-bug order)
__device__ float g_nrm[B_ * N_];        // ||y_n||^2
__device__ float g_R[B_];               // max_n ||y_n||^2

// ---------------------------------------------------------------------------
// helpers
// ---------------------------------------------------------------------------
__device__ __forceinline__ uint32_t s2u(const void* p) {
    uint32_t a;
    asm("{ .reg .u64 t; cvta.to.shared.u64 t, %1; cvt.u32.u64 %0, t; }" : "=r"(a) : "l"(p));
    return a;
}

__device__ __forceinline__ uint32_t packbf(__nv_bfloat16 a, __nv_bfloat16 b) {
    __nv_bfloat162 t = __halves2bfloat162(a, b);
    return *reinterpret_cast<uint32_t*>(&t);
}

// hi/lo split of a float pair -> two packed bf16x2
__device__ __forceinline__ uint32_t split2(float a, float b, uint32_t& lo) {
    __nv_bfloat16 ha = __float2bfloat16(a), hb = __float2bfloat16(b);
    lo = packbf(__float2bfloat16(a - __bfloat162float(ha)),
                __float2bfloat16(b - __bfloat162float(hb)));
    return packbf(ha, hb);
}

__device__ __forceinline__ void ldsm4(uint32_t* r, uint32_t addr) {
    asm volatile("ldmatrix.sync.aligned.m8n8.x4.shared.b16 {%0,%1,%2,%3}, [%4];"
                 : "=r"(r[0]), "=r"(r[1]), "=r"(r[2]), "=r"(r[3]) : "r"(addr));
}

__device__ __forceinline__ void ldsm4t(uint32_t* r, uint32_t addr) {
    asm volatile("ldmatrix.sync.aligned.m8n8.x4.trans.shared.b16 {%0,%1,%2,%3}, [%4];"
                 : "=r"(r[0]), "=r"(r[1]), "=r"(r[2]), "=r"(r[3]) : "r"(addr));
}

__device__ __forceinline__ void mma16816(float* d, const uint32_t* a, const uint32_t* b) {
    asm volatile(
        "mma.sync.aligned.m16n8k16.row.col.f32.bf16.bf16.f32 "
        "{%0,%1,%2,%3}, {%4,%5,%6,%7}, {%8,%9}, {%0,%1,%2,%3};"
        : "+f"(d[0]), "+f"(d[1]), "+f"(d[2]), "+f"(d[3])
        : "r"(a[0]), "r"(a[1]), "r"(a[2]), "r"(a[3]), "r"(b[0]), "r"(b[1]));
}

// ---------------------------------------------------------------------------
__global__ void init_kernel() {
    if (threadIdx.x < B_) g_R[threadIdx.x] = 0.f;
}

// ---------------------------------------------------------------------------
// conv1: y[b][n][o] = b1[o] + sum_c x[b][c][n] * W1[o][c]
// ---------------------------------------------------------------------------
__global__ __launch_bounds__(256) void conv1_kernel(const float* __restrict__ x,
                                                    const float* __restrict__ W1,
                                                    const float* __restrict__ b1) {
    __shared__ float Xs[32 * 68];
    __shared__ float Wt[32 * 132];

    const int t  = threadIdx.x;
    const int n0 = blockIdx.x * 64;
    const int b  = blockIdx.y;
    const int ty = t >> 4, tx = t & 15;
    const int r0 = ty * 4;
    const int o0 = tx * 8;
    const float* xb = x + (size_t)b * C_ * N_;

    float acc[4][8];
#pragma unroll
    for (int i = 0; i < 4; i++)
#pragma unroll
        for (int j = 0; j < 8; j++) acc[i][j] = 0.f;

    for (int c0 = 0; c0 < C_; c0 += 32) {
        __syncthreads();
        for (int e = t; e < 32 * 16; e += 256) {
            int cc = e >> 4, k4 = (e & 15) << 2;
            *(float4*)&Xs[cc * 68 + k4] =
                *(const float4*)(xb + (size_t)(c0 + cc) * N_ + n0 + k4);
        }
        for (int e = t; e < 128 * 8; e += 256) {
            int o = e >> 3, c4 = (e & 7) << 2;
            float4 w = *(const float4*)(W1 + (size_t)o * C_ + c0 + c4);
            Wt[(c4 + 0) * 132 + o] = w.x;
            Wt[(c4 + 1) * 132 + o] = w.y;
            Wt[(c4 + 2) * 132 + o] = w.z;
            Wt[(c4 + 3) * 132 + o] = w.w;
        }
        __syncthreads();
#pragma unroll 8
        for (int cc = 0; cc < 32; cc++) {
            float xv[4];
#pragma unroll
            for (int i = 0; i < 4; i++) xv[i] = Xs[cc * 68 + r0 + i];
            float4 wa = *(float4*)&Wt[cc * 132 + o0];
            float4 wb = *(float4*)&Wt[cc * 132 + o0 + 4];
            float wv[8] = {wa.x, wa.y, wa.z, wa.w, wb.x, wb.y, wb.z, wb.w};
#pragma unroll
            for (int i = 0; i < 4; i++)
#pragma unroll
                for (int j = 0; j < 8; j++) acc[i][j] += xv[i] * wv[j];
        }
    }

    float bv[8];
#pragma unroll
    for (int j = 0; j < 8; j++) bv[j] = b1[o0 + j];
#pragma unroll
    for (int i = 0; i < 4; i++) {
        float* dst = g_y + (size_t)(b * N_ + n0 + r0 + i) * C2_ + o0;
        *(float4*)dst = make_float4(acc[i][0] + bv[0], acc[i][1] + bv[1],
                                    acc[i][2] + bv[2], acc[i][3] + bv[3]);
        *(float4*)(dst + 4) = make_float4(acc[i][4] + bv[4], acc[i][5] + bv[5],
                                          acc[i][6] + bv[6], acc[i][7] + bv[7]);
    }
}

// ---------------------------------------------------------------------------
// norms: nrm[b][n] = ||y_n||^2 ; R[b] = max_n nrm
// ---------------------------------------------------------------------------
__global__ __launch_bounds__(256) void norm_kernel() {
    const int b = blockIdx.y;
    const int n = blockIdx.x * 256 + threadIdx.x;
    const float* yr = g_y + ((size_t)b * N_ + n) * C2_;
    float s = 0.f;
#pragma unroll
    for (int k = 0; k < 32; k++) {
        float4 v = *(const float4*)(yr + k * 4);
        s += v.x * v.x + v.y * v.y + v.z * v.z + v.w * v.w;
    }
    g_nrm[(size_t)b * N_ + n] = s;

    __shared__ float red[8];
    float m = s;
#pragma unroll
    for (int o = 16; o > 0; o >>= 1) m = fmaxf(m, __shfl_xor_sync(0xffffffffu, m, o));
    if ((threadIdx.x & 31) == 0) red[threadIdx.x >> 5] = m;
    __syncthreads();
    if (threadIdx.x < 8) {
        float mm = red[threadIdx.x];
#pragma unroll
        for (int o = 4; o > 0; o >>= 1) mm = fmaxf(mm, __shfl_xor_sync(0xffu, mm, o));
        if (threadIdx.x == 0) atomicMax((int*)&g_R[b], __float_as_int(mm));
    }
}

// ---------------------------------------------------------------------------
// mma.sync flash attention. 256 threads = 8 warps; warp w owns query rows
// w*16..w*16+15. Per 64-key chunk: S = QK^T (3-pass hi/lo), p = exp(s - mt),
// O += P*V (3-pass hi/lo, V fetched with ldmatrix.trans from the K tile).
// ---------------------------------------------------------------------------
__global__ __launch_bounds__(256, 1) void attn_mma_kernel() {
    extern __shared__ __align__(16) char sm[];
    const uint32_t sb = s2u(sm);

    const int t = threadIdx.x;
    const int w = t >> 5, lane = t & 31;
    const int n0 = blockIdx.x * QT;
    const int b  = blockIdx.y;
    const float* yb = g_y + (size_t)b * N_ * C2_;

    // fixed softmax bases for this thread's two rows
    const int r0 = w * 16 + (lane >> 2);
    const int r1 = r0 + 8;
    const float Rb = g_R[b];
    const float mt0 = sqrtf(g_nrm[(size_t)b * N_ + n0 + r0] * Rb);
    const float mt1 = sqrtf(g_nrm[(size_t)b * N_ + n0 + r1] * Rb);

    // ---- Q tile -> smem hi/lo, swizzled [row 256B][chunk16 ^ (row&7)] ----
    {
        const int row = t >> 1, half = t & 1;
        const float* src = yb + (size_t)(n0 + row) * C2_;
#pragma unroll
        for (int f8 = 0; f8 < 8; f8++) {
            const int c16 = half * 8 + f8;
            float4 v0 = *(const float4*)(src + c16 * 8);
            float4 v1 = *(const float4*)(src + c16 * 8 + 4);
            uint32_t lo0, lo1, lo2, lo3;
            uint32_t h0 = split2(v0.x, v0.y, lo0);
            uint32_t h1 = split2(v0.z, v0.w, lo1);
            uint32_t h2 = split2(v1.x, v1.y, lo2);
            uint32_t h3 = split2(v1.z, v1.w, lo3);
            const uint32_t off = (uint32_t)row * 256 + ((c16 ^ (row & 7)) << 4);
            *(uint4*)(sm + OFF_QHI + off) = make_uint4(h0, h1, h2, h3);
            *(uint4*)(sm + OFF_QLO + off) = make_uint4(lo0, lo1, lo2, lo3);
        }
    }

    // ldmatrix lane-address precompute
    const int laneh = lane >> 4;                       // 0/1
    const int rowA  = w * 16 + (lane & 15);            // Q row for A frags
    const int rA7   = rowA & 7;
    const uint32_t aQhi = sb + OFF_QHI + (uint32_t)rowA * 256;
    const uint32_t aQlo = sb + OFF_QLO + (uint32_t)rowA * 256;
    const int keyS = (lane & 7) + (laneh << 3);        // S-phase B key-in-pair
    const int cS   = (lane >> 3) & 1;
    const int l7   = lane & 7;
    const int keyV = lane & 15;                        // PV-phase V key offset

    float o[16][4];
#pragma unroll
    for (int n = 0; n < 16; n++)
#pragma unroll
        for (int e = 0; e < 4; e++) o[n][e] = 0.f;
    float lacc0 = 0.f, lacc1 = 0.f;

    for (int ci = 0; ci < NCHUNK; ci++) {
        __syncthreads();  // previous PV (and Q store on iter 0) done

        // ---- load & convert 64-key chunk (hi/lo) ----
        {
            const int j = t >> 2, qi = t & 3;
            const float* src = yb + (size_t)(ci * KT + j) * C2_;
            const int j7 = j & 7;
#pragma unroll
            for (int q = 0; q < 4; q++) {
                const int c16 = qi * 4 + q;
                float4 v0 = *(const float4*)(src + c16 * 8);
                float4 v1 = *(const float4*)(src + c16 * 8 + 4);
                uint32_t lo0, lo1, lo2, lo3;
                uint32_t h0 = split2(v0.x, v0.y, lo0);
                uint32_t h1 = split2(v0.z, v0.w, lo1);
                uint32_t h2 = split2(v1.x, v1.y, lo2);
                uint32_t h3 = split2(v1.z, v1.w, lo3);
                const uint32_t off = (uint32_t)j * 256 + ((c16 ^ j7) << 4);
                *(uint4*)(sm + OFF_YHI + off) = make_uint4(h0, h1, h2, h3);
                *(uint4*)(sm + OFF_YLO + off) = make_uint4(lo0, lo1, lo2, lo3);
            }
        }
        __syncthreads();

        // ---- S = Q K^T : 8 ktiles (16 feats), 8 n-cols per tile x 8 tiles ----
        float s[8][4];
#pragma unroll
        for (int n = 0; n < 8; n++)
#pragma unroll
            for (int e = 0; e < 4; e++) s[n][e] = 0.f;

#pragma unroll
        for (int k = 0; k < 8; k++) {
            const int cA = 2 * k + laneh;
            uint32_t qh[4], ql[4];
            ldsm4(qh, aQhi + ((cA ^ rA7) << 4));
            ldsm4(ql, aQlo + ((cA ^ rA7) << 4));
            const int cB = 2 * k + cS;
#pragma unroll
            for (int np = 0; np < 4; np++) {
                const uint32_t rb = (uint32_t)(np * 16 + keyS) * 256 +
                                    (uint32_t)((cB ^ l7) << 4);
                uint32_t bh[4], bl[4];
                ldsm4(bh, sb + OFF_YHI + rb);
                ldsm4(bl, sb + OFF_YLO + rb);
                mma16816(s[2 * np],     qh, bh);
                mma16816(s[2 * np + 1], qh, bh + 2);
                mma16816(s[2 * np],     qh, bl);
                mma16816(s[2 * np + 1], qh, bl + 2);
                mma16816(s[2 * np],     ql, bh);
                mma16816(s[2 * np + 1], ql, bh + 2);
            }
        }

        // ---- softmax (fixed base) + pack P into A-fragments hi/lo ----
        uint32_t ph[16], pl[16];
#pragma unroll
        for (int j = 0; j < 8; j++) {
            float p0 = __expf(s[j][0] - mt0);
            float p1 = __expf(s[j][1] - mt0);
            float p2 = __expf(s[j][2] - mt1);
            float p3 = __expf(s[j][3] - mt1);
            lacc0 += p0 + p1;
            lacc1 += p2 + p3;
            const int idx = (j >> 1) * 4 + (j & 1) * 2;
            ph[idx]     = split2(p0, p1, pl[idx]);
            ph[idx + 1] = split2(p2, p3, pl[idx + 1]);
        }

        // ---- O += P V : V via ldmatrix.trans on the same K tile ----
#pragma unroll
        for (int fp = 0; fp < 8; fp++) {
#pragma unroll
            for (int K = 0; K < 4; K++) {
                const uint32_t rb = (uint32_t)(K * 16 + keyV) * 256 +
                                    (uint32_t)(((fp * 2 + laneh) ^ l7) << 4);
                uint32_t vh[4], vl[4];
                ldsm4t(vh, sb + OFF_YHI + rb);
                ldsm4t(vl, sb + OFF_YLO + rb);
                mma16816(o[2 * fp],     &ph[4 * K], vh);
                mma16816(o[2 * fp + 1], &ph[4 * K], vh + 2);
                mma16816(o[2 * fp],     &ph[4 * K], vl);
                mma16816(o[2 * fp + 1], &ph[4 * K], vl + 2);
                mma16816(o[2 * fp],     &pl[4 * K], vh);
                mma16816(o[2 * fp + 1], &pl[4 * K], vh + 2);
            }
        }
    }

    // ---- finalize l (reduce across the 4 lanes of each row group) ----
    lacc0 += __shfl_xor_sync(0xffffffffu, lacc0, 1);
    lacc0 += __shfl_xor_sync(0xffffffffu, lacc0, 2);
    lacc1 += __shfl_xor_sync(0xffffffffu, lacc1, 1);
    lacc1 += __shfl_xor_sync(0xffffffffu, lacc1, 2);
    const float inv0 = 1.0f / lacc0;
    const float inv1 = 1.0f / lacc1;

    // ---- epilogue: normalize, store flat [n][c2] (torch-bug order) ----
    float* dst0 = g_att + (size_t)b * N_ * C2_ + (size_t)(n0 + r0) * C2_;
    float* dst1 = g_att + (size_t)b * N_ * C2_ + (size_t)(n0 + r1) * C2_;
    const int fbase = 2 * (lane & 3);
#pragma unroll
    for (int n = 0; n < 16; n++) {
        const int f = n * 8 + fbase;
        *(float2*)(dst0 + f) = make_float2(o[n][0] * inv0, o[n][1] * inv0);
        *(float2*)(dst1 + f) = make_float2(o[n][2] * inv1, o[n][3] * inv1);
    }
}

// ---------------------------------------------------------------------------
// conv2 + scale + residual
// ---------------------------------------------------------------------------
__global__ __launch_bounds__(256) void conv2_kernel(const float* __restrict__ x,
                                                    const float* __restrict__ W2,
                                                    const float* __restrict__ b2,
                                                    const float* __restrict__ scale,
                                                    float* __restrict__ out) {
    extern __shared__ float smf[];
    float* Ss = smf;
    float* Ws = smf + 128 * 68;

    const int t  = threadIdx.x;
    const int n0 = blockIdx.x * 64;
    const int o0 = blockIdx.y * 64;
    const int b  = blockIdx.z;
    const int ty = t >> 4, tx = t & 15;
    const int r0 = ty * 4;
    const int c0 = tx * 4;
    const float* sbp = g_att + (size_t)b * N_ * C2_;

    for (int e = t; e < 128 * 16; e += 256) {
        int row = e >> 4, k4 = (e & 15) << 2;
        *(float4*)&Ss[row * 68 + k4] = *(const float4*)(sbp + (size_t)row * N_ + n0 + k4);
    }
    for (int e = t; e < 64 * 32; e += 256) {
        int o = e >> 5, c4 = (e & 31) << 2;
        *(float4*)&Ws[o * 132 + c4] = *(const float4*)(W2 + (size_t)(o0 + o) * C2_ + c4);
    }
    __syncthreads();

    float acc[4][4];
#pragma unroll
    for (int i = 0; i < 4; i++)
#pragma unroll
        for (int j = 0; j < 4; j++) acc[i][j] = 0.f;

#pragma unroll 4
    for (int c = 0; c < 128; c++) {
        float wv[4];
#pragma unroll
        for (int i = 0; i < 4; i++) wv[i] = Ws[(r0 + i) * 132 + c];
        float4 sv = *(float4*)&Ss[c * 68 + c0];
#pragma unroll
        for (int i = 0; i < 4; i++) {
            acc[i][0] += wv[i] * sv.x;
            acc[i][1] += wv[i] * sv.y;
            acc[i][2] += wv[i] * sv.z;
            acc[i][3] += wv[i] * sv.w;
        }
    }

#pragma unroll
    for (int i = 0; i < 4; i++) {
        int oo = o0 + r0 + i;
        float sc = scale[oo];
        float bi = b2[oo];
        size_t idx = ((size_t)(b * C_ + oo)) * N_ + n0 + c0;
        float4 xv = *(const float4*)(x + idx);
        float4 r;
        r.x = sc * (acc[i][0] + bi) + xv.x;
        r.y = sc * (acc[i][1] + bi) + xv.y;
        r.z = sc * (acc[i][2] + bi) + xv.z;
        r.w = sc * (acc[i][3] + bi) + xv.w;
        *(float4*)(out + idx) = r;
    }
}

// ---------------------------------------------------------------------------
extern "C" void kernel_launch(void* const* d_in, const int* in_sizes, int n_in,
                              void* d_out, int out_size) {
    const float* x     = (const float*)d_in[0];
    const float* W1    = (const float*)d_in[1];
    const float* b1    = (const float*)d_in[2];
    const float* W2    = (const float*)d_in[3];
    const float* b2    = (const float*)d_in[4];
    const float* scale = (const float*)d_in[5];
    float* out = (float*)d_out;

    constexpr int CONV2_SMEM = (128 * 68 + 64 * 132) * 4;
    cudaFuncSetAttribute(attn_mma_kernel, cudaFuncAttributeMaxDynamicSharedMemorySize, ATTN_DYN);
    cudaFuncSetAttribute(conv2_kernel, cudaFuncAttributeMaxDynamicSharedMemorySize, CONV2_SMEM);

    init_kernel<<<1, 32>>>();
    conv1_kernel<<<dim3(N_ / 64, B_), 256>>>(x, W1, b1);
    norm_kernel<<<dim3(N_ / 256, B_), 256>>>();
    attn_mma_kernel<<<dim3(N_ / QT, B_), 256, ATTN_DYN>>>();
    conv2_kernel<<<dim3(N_ / 64, C_ / 64, B_), 256, CONV2_SMEM>>>(x, W2, b2, scale, out);
}